// round 14
// baseline (speedup 1.0000x reference)
#include <cuda_runtime.h>
#include <cuda_fp16.h>

#define TT   4
#define NN   20000
#define EE   640000
#define DIN  256
#define DOUT 128
#define MAT  (DIN * DOUT)      // 32768
#define MSQ  (DIN * DIN)       // 65536
#define SLOPE 0.22916666666666666f

typedef unsigned long long ull;

// ---------------- scratch (__device__ globals; no allocation) ----------------
__device__ float  g_scores[TT * NN];
__device__ float  g_xt[TT * MAT];
__device__ float  g_Wn[(TT + 1) * MAT];
__device__ __half g_Wh[TT * MAT];
__device__ float  g_WT[6 * MSQ];
__device__ float  g_WX[3 * TT * MAT];
__device__ float  g_z[MAT];
__device__ float  g_rW[MAT];
__device__ __half g_y[(size_t)TT * NN * DOUT];
__device__ int    g_deg[TT * NN];
__device__ int    g_off[TT * (NN + 1)];
__device__ int    g_cur[TT * NN];
__device__ int2   g_csr[(size_t)TT * EE];
__device__ int    g_hist[TT * 4096];
// flags (zero-init; reset at end of each replay in gather_only)
__device__ int    g_fscore[TT];   // 2500 each
__device__ int    g_fdeg[TT];     // 2500 each
__device__ int    g_fprep;        // 1664
__device__ int    g_fsel[TT];     // 1 each
__device__ int    g_fscan0;       // 1
__device__ int    g_flagWX;       // 32 (t=0 WX blocks)
__device__ int    g_flagA[TT];    // 32 each

// ---------------- helpers ----------------
__device__ __forceinline__ unsigned ord_of(float f) {
    unsigned b = __float_as_uint(f);
    return b ^ ((b & 0x80000000u) ? 0xFFFFFFFFu : 0x80000000u);
}
__device__ __forceinline__ float sigmoidf_(float x) {
    return 1.0f / (1.0f + expf(-x));
}
__device__ __forceinline__ float2 upk(ull v) {
    float2 r;
    asm("mov.b64 {%0, %1}, %2;" : "=f"(r.x), "=f"(r.y) : "l"(v));
    return r;
}
__device__ __forceinline__ ull dup2(float a) {
    ull r;
    asm("mov.b64 %0, {%1, %1};" : "=l"(r) : "f"(a));
    return r;
}
__device__ __forceinline__ unsigned smaddr(const void* p) {
    return (unsigned)__cvta_generic_to_shared(p);
}
__device__ __forceinline__ void flag_release(int* f) {
    __threadfence();
    __syncthreads();
    if (threadIdx.x == 0) atomicAdd(f, 1);
}
__device__ __forceinline__ void flag_wait(const int* f, int target) {
    if (threadIdx.x == 0) {
        while (*(volatile const int*)f < target) __nanosleep(1024);
    }
    __syncthreads();
    __threadfence();
}

// ===== small GEMM: 8x128 tile, K=256, up to 3 A-mats sharing B (256 thr) ======
#define KT 32
template <int NMAT>
__device__ __forceinline__ void gemmR8(const float* __restrict__ AT0,
                                       const float* __restrict__ AT1,
                                       const float* __restrict__ AT2,
                                       const float* __restrict__ Bmat,
                                       int i0, ull a0[2], ull a1[2], ull a2[2],
                                       char* sm) {
    float (*Bs)[128] = (float(*)[128])sm;
    float (*As)[8]   = (float(*)[8])(sm + KT * 128 * 4);
    int tid = threadIdx.x;
    int ti = tid & 7, tj = tid >> 3;
    int brow = tid >> 5, bcol = (tid & 31) * 4;
    int akk = tid >> 3, aii = tid & 7;

    float4 pb[4];
    float pa0, pa1, pa2;
#pragma unroll
    for (int l = 0; l < 4; l++)
        pb[l] = *(const float4*)&Bmat[(brow + 8 * l) * 128 + bcol];
    pa0 = AT0[akk * DIN + i0 + aii];
    if (NMAT > 1) pa1 = AT1[akk * DIN + i0 + aii];
    if (NMAT > 2) pa2 = AT2[akk * DIN + i0 + aii];

    for (int k0 = 0; k0 < DIN; k0 += KT) {
#pragma unroll
        for (int l = 0; l < 4; l++)
            *(float4*)&Bs[brow + 8 * l][bcol] = pb[l];
        As[0 * KT + akk][aii] = pa0;
        if (NMAT > 1) As[1 * KT + akk][aii] = pa1;
        if (NMAT > 2) As[2 * KT + akk][aii] = pa2;
        __syncthreads();
        int kn = k0 + KT;
        if (kn < DIN) {
#pragma unroll
            for (int l = 0; l < 4; l++)
                pb[l] = *(const float4*)&Bmat[(kn + brow + 8 * l) * 128 + bcol];
            pa0 = AT0[(kn + akk) * DIN + i0 + aii];
            if (NMAT > 1) pa1 = AT1[(kn + akk) * DIN + i0 + aii];
            if (NMAT > 2) pa2 = AT2[(kn + akk) * DIN + i0 + aii];
        }
#pragma unroll
        for (int kk = 0; kk < KT; kk++) {
            ull b0 = *(const ull*)&Bs[kk][tj * 4 + 0];
            ull b1 = *(const ull*)&Bs[kk][tj * 4 + 2];
            {
                ull av = dup2(As[0 * KT + kk][ti]);
                asm("fma.rn.f32x2 %0, %1, %2, %0;" : "+l"(a0[0]) : "l"(av), "l"(b0));
                asm("fma.rn.f32x2 %0, %1, %2, %0;" : "+l"(a0[1]) : "l"(av), "l"(b1));
            }
            if (NMAT > 1) {
                ull av = dup2(As[1 * KT + kk][ti]);
                asm("fma.rn.f32x2 %0, %1, %2, %0;" : "+l"(a1[0]) : "l"(av), "l"(b0));
                asm("fma.rn.f32x2 %0, %1, %2, %0;" : "+l"(a1[1]) : "l"(av), "l"(b1));
            }
            if (NMAT > 2) {
                ull av = dup2(As[2 * KT + kk][ti]);
                asm("fma.rn.f32x2 %0, %1, %2, %0;" : "+l"(a2[0]) : "l"(av), "l"(b0));
                asm("fma.rn.f32x2 %0, %1, %2, %0;" : "+l"(a2[1]) : "l"(av), "l"(b1));
            }
        }
        __syncthreads();
    }
}

// ---- gruA (32 blocks) --------------------------------------------------------
__device__ __forceinline__ void dev_gruA(int t, int bx,
                                         const float* __restrict__ bz,
                                         const float* __restrict__ br,
                                         char* sm, bool wait_wx) {
    int i0 = bx * 8;
    ull a0[2] = {0, 0}, a1[2] = {0, 0};
    gemmR8<2>(g_WT + 1 * MSQ, g_WT + 3 * MSQ, (const float*)0,
              g_Wn + t * MAT, i0, a0, a1, a0, sm);
    if (wait_wx) flag_wait(&g_flagWX, 32);
    int ti = threadIdx.x & 7, tj = threadIdx.x >> 3;
    int row = i0 + ti, col = tj * 4;
    const float* WXz = g_WX + (0 * TT + t) * MAT;
    const float* WXr = g_WX + (1 * TT + t) * MAT;
    const float* Wt  = g_Wn + t * MAT;
#pragma unroll
    for (int j = 0; j < 2; j++) {
        int o = row * DOUT + col + 2 * j;
        float2 az = upk(a0[j]), ar = upk(a1[j]);
        float2 xz = *(const float2*)&WXz[o];
        float2 xr = *(const float2*)&WXr[o];
        float2 vz = *(const float2*)&bz[o];
        float2 vr = *(const float2*)&br[o];
        float2 wv = *(const float2*)&Wt[o];
        float2 z2, rw2;
        z2.x = sigmoidf_(az.x + xz.x + vz.x);
        z2.y = sigmoidf_(az.y + xz.y + vz.y);
        rw2.x = sigmoidf_(ar.x + xr.x + vr.x) * wv.x;
        rw2.y = sigmoidf_(ar.y + xr.y + vr.y) * wv.y;
        *(float2*)&g_z[o] = z2;
        *(float2*)&g_rW[o] = rw2;
    }
    flag_release(&g_flagA[t]);
}

// ---- gruB (32 blocks) --------------------------------------------------------
__device__ __forceinline__ void dev_gruB(int t, int bx,
                                         const float* __restrict__ bh, char* sm) {
    flag_wait(&g_flagA[t], 32);
    int i0 = bx * 8;
    ull a0[2] = {0, 0};
    gemmR8<1>(g_WT + 5 * MSQ, (const float*)0, (const float*)0,
              g_rW, i0, a0, a0, a0, sm);
    int ti = threadIdx.x & 7, tj = threadIdx.x >> 3;
    int row = i0 + ti, col = tj * 4;
    const float* WXh = g_WX + (2 * TT + t) * MAT;
    const float* Wt  = g_Wn + t * MAT;
    float* Wnx = g_Wn + (t + 1) * MAT;
    __half* Whx = g_Wh + t * MAT;
#pragma unroll
    for (int j = 0; j < 2; j++) {
        int o = row * DOUT + col + 2 * j;
        float2 ah = upk(a0[j]);
        float2 xh = *(const float2*)&WXh[o];
        float2 vh = *(const float2*)&bh[o];
        float2 wv = *(const float2*)&Wt[o];
        float2 z2 = *(const float2*)&g_z[o];
        float hx = tanhf(ah.x + xh.x + vh.x);
        float hy = tanhf(ah.y + xh.y + vh.y);
        float2 wn;
        wn.x = wv.x + z2.x * (hx - wv.x);
        wn.y = wv.y + z2.y * (hy - wv.y);
        *(float2*)&Wnx[o] = wn;
        *(__half2*)&Whx[o] = __float22half2_rn(wn);
    }
}

// ---- CSR fill body ------------------------------------------------------------
__device__ __forceinline__ void dev_fill(int t, int bx,
                                         const int* __restrict__ ei,
                                         const float* __restrict__ w) {
    int e = bx * 256 + threadIdx.x;
    const int* dst = ei + (size_t)t * 2 * EE;
    const int* src = dst + EE;
    int d = dst[e];
    int pos = atomicAdd(&g_cur[t * NN + d], 1);
    g_csr[(size_t)t * EE + pos] = make_int2(src[e], __float_as_int(w[(size_t)t * EE + e]));
}

// ---- scan (256 threads): CSR offsets + deg re-zero ----------------------------
__device__ void do_scan(int t) {
    __shared__ int part[256];
    int tid = threadIdx.x;
    int* deg = g_deg + t * NN;
    int* off = g_off + t * (NN + 1);
    int* cur = g_cur + t * NN;
    int base = tid * 80;
    int sum = 0;
    for (int i = 0; i < 80; i++) {
        int n = base + i;
        if (n < NN) sum += deg[n];
    }
    part[tid] = sum;
    __syncthreads();
    for (int o = 1; o < 256; o <<= 1) {
        int v = (tid >= o) ? part[tid - o] : 0;
        __syncthreads();
        part[tid] += v;
        __syncthreads();
    }
    int run = tid ? part[tid - 1] : 0;
    for (int i = 0; i < 80; i++) {
        int n = base + i;
        if (n < NN) {
            int d = deg[n];
            off[n] = run;
            cur[n] = run;
            deg[n] = 0;
            run += d;
        }
    }
    if (tid == 255) off[NN] = run;
}

// ---- select (256 threads): top-128 + xt build ----------------------------------
__device__ void do_select(int t, const float* __restrict__ embs) {
    int tid = threadIdx.x;   // 256
    __shared__ int part[256];
    __shared__ int sB, sAbove;
    __shared__ unsigned cnt_gt, cnt_cand;
    __shared__ unsigned sel_ord[DOUT];
    __shared__ int sel_idx[DOUT];
    __shared__ unsigned cand_ord[512];
    __shared__ int cand_idx[512];
    __shared__ int sh_idx[DOUT];
    __shared__ float sh_tanh[DOUT];

    const float* scores = g_scores + t * NN;
    int* hist = g_hist + t * 4096;

    int cnt[16];
    int s = 0;
#pragma unroll
    for (int j = 0; j < 16; j++) {
        int bin = 4095 - (tid * 16 + j);
        cnt[j] = hist[bin];
        s += cnt[j];
    }
    part[tid] = s;
    if (tid == 0) { cnt_gt = 0; cnt_cand = 0; }
    __syncthreads();
    for (int o = 1; o < 256; o <<= 1) {
        int v = (tid >= o) ? part[tid - o] : 0;
        __syncthreads();
        part[tid] += v;
        __syncthreads();
    }
    int c = tid ? part[tid - 1] : 0;
#pragma unroll
    for (int j = 0; j < 16; j++) {
        int bin = 4095 - (tid * 16 + j);
        if (c < DOUT && c + cnt[j] >= DOUT) { sB = bin; sAbove = c; }
        c += cnt[j];
    }
    __syncthreads();
#pragma unroll
    for (int j = 0; j < 16; j++) hist[4095 - (tid * 16 + j)] = 0;
    int B = sB, above = sAbove, kneed = DOUT - above;

    for (int n = tid; n < NN; n += 256) {
        unsigned ord = ord_of(scores[n]);
        int bucket = ord >> 20;
        if (bucket > B) {
            unsigned pos = atomicAdd(&cnt_gt, 1u);
            sel_ord[pos] = ord; sel_idx[pos] = n;
        } else if (bucket == B) {
            unsigned pos = atomicAdd(&cnt_cand, 1u);
            if (pos < 512) { cand_ord[pos] = ord; cand_idx[pos] = n; }
        }
    }
    __syncthreads();
    int nc = (int)cnt_cand; if (nc > 512) nc = 512;
    for (int ci = tid; ci < nc; ci += 256) {
        unsigned mo = cand_ord[ci];
        int mi = cand_idx[ci];
        int r = 0;
        for (int j = 0; j < nc; j++) {
            unsigned o = cand_ord[j];
            r += (o > mo) || (o == mo && cand_idx[j] < mi);
        }
        if (r < kneed) { sel_ord[above + r] = mo; sel_idx[above + r] = mi; }
    }
    __syncthreads();
    if (tid < DOUT) {
        unsigned mo = sel_ord[tid];
        int mi = sel_idx[tid];
        int r = 0;
#pragma unroll 4
        for (int i = 0; i < DOUT; i++) {
            unsigned o = sel_ord[i];
            r += (o > mo) || (o == mo && sel_idx[i] < mi);
        }
        sh_idx[r] = mi;
        sh_tanh[r] = tanhf(scores[mi]);
    }
    __syncthreads();
    float* xt = g_xt + t * MAT;
    for (int e = tid; e < MAT; e += 256) {
        int j = e >> 8;
        int d = e & 255;
        xt[d * DOUT + j] = embs[((size_t)t * NN + sh_idx[j]) * DIN + d] * sh_tanh[j];
    }
}

// ================= MEGA: front | deg | prep | scan | select | WX | gru0 | fill0
#define MB_SC   10000
#define MB_DG   20000
#define MB_PREP 21664
#define MB_SCAN 21668
#define MB_SEL  21672
#define MB_WX   21800
#define MB_GA   21832
#define MB_GB   21864
#define MB_TOT  (MB_GB + 2500)
#define MEGA_SMEM (KT * 128 * 4 + 3 * KT * 8 * 4)

__global__ void mega_kernel(const float* __restrict__ embs,
                            const float* __restrict__ p,
                            const float* __restrict__ mask,
                            const int* __restrict__ ei,
                            const float* __restrict__ ew,
                            const float* __restrict__ Wz, const float* __restrict__ Uz,
                            const float* __restrict__ Wr, const float* __restrict__ Ur,
                            const float* __restrict__ Wh, const float* __restrict__ Uh,
                            const float* __restrict__ W0,
                            const float* __restrict__ bz, const float* __restrict__ br,
                            const float* __restrict__ bh) {
    __shared__ __align__(16) char sm[MEGA_SMEM];
    int b = blockIdx.x;
    int tid = threadIdx.x;
    if (b < MB_SC) {
        __shared__ float sp[DIN];
        sp[tid] = p[tid];
        __syncthreads();
        int t = b / 2500;
        int warp = tid >> 5, lane = tid & 31;
        int n = (b % 2500) * 8 + warp;
        const float* xr = embs + ((size_t)t * NN + n) * DIN;
        float4 x0 = *(const float4*)&xr[lane * 4];
        float4 x1 = *(const float4*)&xr[128 + lane * 4];
        float4 p0 = *(const float4*)&sp[lane * 4];
        float4 p1 = *(const float4*)&sp[128 + lane * 4];
        float s = x0.x * p0.x + x0.y * p0.y + x0.z * p0.z + x0.w * p0.w
                + x1.x * p1.x + x1.y * p1.y + x1.z * p1.z + x1.w * p1.w;
        float q = p0.x * p0.x + p0.y * p0.y + p0.z * p0.z + p0.w * p0.w
                + p1.x * p1.x + p1.y * p1.y + p1.z * p1.z + p1.w * p1.w;
#pragma unroll
        for (int o = 16; o > 0; o >>= 1) {
            s += __shfl_down_sync(0xFFFFFFFFu, s, o);
            q += __shfl_down_sync(0xFFFFFFFFu, q, o);
        }
        if (lane == 0) {
            float sc = s * rsqrtf(q) + mask[t * NN + n];
            g_scores[t * NN + n] = sc;
            atomicAdd(&g_hist[t * 4096 + (ord_of(sc) >> 20)], 1);
        }
        flag_release(&g_fscore[t]);
    } else if (b < MB_DG) {
        int idx = b - MB_SC;
        int t = idx / 2500;
        int e = (idx % 2500) * 256 + tid;
        const int* dst = ei + (size_t)t * 2 * EE;
        atomicAdd(&g_deg[t * NN + dst[e]], 1);
        flag_release(&g_fdeg[t]);
    } else if (b < MB_PREP) {
        int idx = (b - MB_DG) * 256 + tid;
        const float* srcs[6] = {Wz, Uz, Wr, Ur, Wh, Uh};
        if (idx < 6 * MSQ) {
            int m = idx >> 16;
            int e = idx & 0xFFFF;
            int k = e >> 8, i = e & 255;
            g_WT[idx] = srcs[m][i * DIN + k];
        } else {
            int e = idx - 6 * MSQ;
            g_Wn[e] = W0[e];
        }
        flag_release(&g_fprep);
    } else if (b < MB_SCAN) {
        int t = b - MB_PREP;
        flag_wait(&g_fdeg[t], 2500);
        do_scan(t);
        if (t == 0) flag_release(&g_fscan0);
    } else if (b < MB_SEL) {
        int t = b - MB_SCAN;
        flag_wait(&g_fscore[t], 2500);
        do_select(t, embs);
        flag_release(&g_fsel[t]);
    } else if (b < MB_WX) {
        int idx = b - MB_SEL;
        int t = idx >> 5, i0 = (idx & 31) * 8;
        flag_wait(&g_fprep, 1664);
        flag_wait(&g_fsel[t], 1);
        ull a0[2] = {0, 0}, a1[2] = {0, 0}, a2[2] = {0, 0};
        gemmR8<3>(g_WT + 0 * MSQ, g_WT + 2 * MSQ, g_WT + 4 * MSQ,
                  g_xt + t * MAT, i0, a0, a1, a2, sm);
        int ti = tid & 7, tj = tid >> 3;
        int base = (i0 + ti) * DOUT + tj * 4;
#pragma unroll
        for (int j = 0; j < 2; j++) {
            *(ull*)&g_WX[(0 * TT + t) * MAT + base + 2 * j] = a0[j];
            *(ull*)&g_WX[(1 * TT + t) * MAT + base + 2 * j] = a1[j];
            *(ull*)&g_WX[(2 * TT + t) * MAT + base + 2 * j] = a2[j];
        }
        if (t == 0) flag_release(&g_flagWX);
    } else if (b < MB_GA) {
        flag_wait(&g_fprep, 1664);      // gemm reads g_WT and g_Wn(0)
        dev_gruA(0, b - MB_WX, bz, br, sm, true);
    } else if (b < MB_GB) {
        dev_gruB(0, b - MB_GA, bh, sm);
    } else {
        flag_wait(&g_fscan0, 1);
        dev_fill(0, b - MB_GB, ei, ew);
    }
}

// ================= tensor-core sgemm: y_t = embs_t @ Wh_t (fp32->fp16 on load)
#define BM 64
#define BN 128
#define SGB ((NN + BM - 1) / BM)   // 313
#define ASTRIDE 40
#define BSTRIDE 136

__device__ __forceinline__ void dev_sgemm(int t, int bx,
                                          const float* __restrict__ embs, char* sm) {
    __half* Ah = (__half*)sm;
    __half* Bh = (__half*)(sm + 64 * ASTRIDE * 2);
    const float* A = embs + (size_t)t * NN * DIN;
    const __half* B = g_Wh + t * MAT;
    __half* C = g_y + (size_t)t * NN * DOUT;
    int tid = threadIdx.x, lane = tid & 31, wid = tid >> 5;
    int wm = wid >> 2, wq = wid & 3;
    int bm = bx * BM;

    float c[2][4][4];
#pragma unroll
    for (int ma = 0; ma < 2; ma++)
#pragma unroll
        for (int na = 0; na < 4; na++)
#pragma unroll
            for (int i = 0; i < 4; i++) c[ma][na][i] = 0.0f;

    int arow = tid >> 2, acol = (tid & 3) * 8;
    int agr = bm + arow;

    for (int k0 = 0; k0 < DIN; k0 += 32) {
        float4 af0 = make_float4(0.f, 0.f, 0.f, 0.f), af1 = af0;
        if (agr < NN) {
            af0 = *(const float4*)&A[(size_t)agr * DIN + k0 + acol];
            af1 = *(const float4*)&A[(size_t)agr * DIN + k0 + acol + 4];
        }
        *(__half2*)&Ah[arow * ASTRIDE + acol + 0] = __floats2half2_rn(af0.x, af0.y);
        *(__half2*)&Ah[arow * ASTRIDE + acol + 2] = __floats2half2_rn(af0.z, af0.w);
        *(__half2*)&Ah[arow * ASTRIDE + acol + 4] = __floats2half2_rn(af1.x, af1.y);
        *(__half2*)&Ah[arow * ASTRIDE + acol + 6] = __floats2half2_rn(af1.z, af1.w);
#pragma unroll
        for (int pp = 0; pp < 2; pp++) {
            int q = tid + pp * 256;
            int brr = q >> 4, bcc = (q & 15) * 8;
            *(uint4*)&Bh[brr * BSTRIDE + bcc] = *(const uint4*)&B[(k0 + brr) * BN + bcc];
        }
        __syncthreads();
#pragma unroll
        for (int ks = 0; ks < 32; ks += 16) {
            unsigned bf[4][2];
#pragma unroll
            for (int na = 0; na < 4; na++) {
                int r = ks + (lane & 15);
                unsigned ad = smaddr(&Bh[r * BSTRIDE + wq * 32 + na * 8]);
                asm volatile("ldmatrix.sync.aligned.m8n8.x2.trans.shared.b16 {%0,%1}, [%2];"
                             : "=r"(bf[na][0]), "=r"(bf[na][1]) : "r"(ad));
            }
#pragma unroll
            for (int ma = 0; ma < 2; ma++) {
                int mr = wm * 32 + ma * 16 + (lane & 15);
                int kc = ks + ((lane >> 4) << 3);
                unsigned ad = smaddr(&Ah[mr * ASTRIDE + kc]);
                unsigned a0, a1, a2, a3;
                asm volatile("ldmatrix.sync.aligned.m8n8.x4.shared.b16 {%0,%1,%2,%3}, [%4];"
                             : "=r"(a0), "=r"(a1), "=r"(a2), "=r"(a3) : "r"(ad));
#pragma unroll
                for (int na = 0; na < 4; na++) {
                    asm volatile(
                        "mma.sync.aligned.m16n8k16.row.col.f32.f16.f16.f32 "
                        "{%0,%1,%2,%3}, {%4,%5,%6,%7}, {%8,%9}, {%0,%1,%2,%3};"
                        : "+f"(c[ma][na][0]), "+f"(c[ma][na][1]),
                          "+f"(c[ma][na][2]), "+f"(c[ma][na][3])
                        : "r"(a0), "r"(a1), "r"(a2), "r"(a3),
                          "r"(bf[na][0]), "r"(bf[na][1]));
                }
            }
        }
        __syncthreads();
    }
#pragma unroll
    for (int ma = 0; ma < 2; ma++) {
        int row0 = bm + wm * 32 + ma * 16 + (lane >> 2);
#pragma unroll
        for (int na = 0; na < 4; na++) {
            int col = wq * 32 + na * 8 + (lane & 3) * 2;
            if (row0 < NN)
                *(__half2*)&C[(size_t)row0 * DOUT + col] =
                    __floats2half2_rn(c[ma][na][0], c[ma][na][1]);
            if (row0 + 8 < NN)
                *(__half2*)&C[(size_t)(row0 + 8) * DOUT + col] =
                    __floats2half2_rn(c[ma][na][2], c[ma][na][3]);
        }
    }
}

// ---- gather: 8 edge-rows in flight per warp ----------------------------------
__device__ __forceinline__ void dev_gather(int t, int bx, float* __restrict__ out) {
    int node = bx * 8 + (threadIdx.x >> 5);
    int lane = threadIdx.x & 31;
    const int* off = g_off + t * (NN + 1);
    const int2* csr = g_csr + (size_t)t * EE;
    const __half* y = g_y + (size_t)t * NN * DOUT;
    int beg = off[node], end = off[node + 1];
    float4 acc = make_float4(0.f, 0.f, 0.f, 0.f);
    int e = beg;
    for (; e + 8 <= end; e += 8) {
        int2 cc[8];
        uint2 rr[8];
#pragma unroll
        for (int u = 0; u < 8; u++) cc[u] = csr[e + u];
#pragma unroll
        for (int u = 0; u < 8; u++)
            rr[u] = *(const uint2*)&y[(size_t)cc[u].x * DOUT + lane * 4];
#pragma unroll
        for (int u = 0; u < 8; u++) {
            float wv = __int_as_float(cc[u].y);
            float2 av = __half22float2(*(__half2*)&rr[u].x);
            float2 bv = __half22float2(*(__half2*)&rr[u].y);
            acc.x += wv * av.x;
            acc.y += wv * av.y;
            acc.z += wv * bv.x;
            acc.w += wv * bv.y;
        }
    }
    for (; e < end; e++) {
        int2 c0 = csr[e];
        float w0 = __int_as_float(c0.y);
        uint2 r0 = *(const uint2*)&y[(size_t)c0.x * DOUT + lane * 4];
        float2 a0 = __half22float2(*(__half2*)&r0.x), b0 = __half22float2(*(__half2*)&r0.y);
        acc.x += w0 * a0.x; acc.y += w0 * a0.y; acc.z += w0 * b0.x; acc.w += w0 * b0.y;
    }
    acc.x = (acc.x >= 0.f) ? acc.x : SLOPE * acc.x;
    acc.y = (acc.y >= 0.f) ? acc.y : SLOPE * acc.y;
    acc.z = (acc.z >= 0.f) ? acc.z : SLOPE * acc.z;
    acc.w = (acc.w >= 0.f) ? acc.w : SLOPE * acc.w;
    *(float4*)&out[((size_t)t * NN + node) * DOUT + lane * 4] = acc;
}

// ==== pipe P(t): gruA(t+1)|gruB(t+1)(spin)|sgemm(t)|fill(t+1)|gather(t-1) =====
#define PIPE_SMEM (KT * 128 * 4 + 2 * KT * 8 * 4)
__global__ __launch_bounds__(256, 3)
void pipe_kernel(int t_sg, int t_ga, int t_fill, int has_gru,
                 const float* __restrict__ embs,
                 const int* __restrict__ ei, const float* __restrict__ w,
                 const float* __restrict__ bz, const float* __restrict__ br,
                 const float* __restrict__ bh,
                 float* __restrict__ out) {
    __shared__ __align__(16) char sm[PIPE_SMEM];
    int b = blockIdx.x;
    if (has_gru) {
        if (b < 32) { dev_gruA(t_sg + 1, b, bz, br, sm, false); return; }
        if (b < 64) { dev_gruB(t_sg + 1, b - 32, bh, sm); return; }
        b -= 64;
    }
    if (b < SGB) { dev_sgemm(t_sg, b, embs, sm); return; }
    b -= SGB;
    if (t_fill >= 0) {
        if (b < 2500) { dev_fill(t_fill, b, ei, w); return; }
        b -= 2500;
    }
    dev_gather(t_ga, b, out);
}

__global__ void gather_only_kernel(int t, float* __restrict__ out) {
    if (blockIdx.x == 0) {   // reset flags for next graph replay (flags quiescent here)
        int tid = threadIdx.x;
        if (tid < TT) {
            g_fscore[tid] = 0; g_fdeg[tid] = 0; g_fsel[tid] = 0; g_flagA[tid] = 0;
        } else if (tid == TT) {
            g_fprep = 0; g_fscan0 = 0; g_flagWX = 0;
        }
    }
    dev_gather(t, blockIdx.x, out);
}

// ---------------- launcher ----------------
extern "C" void kernel_launch(void* const* d_in, const int* in_sizes, int n_in,
                              void* d_out, int out_size) {
    const float* node_embs  = (const float*)d_in[0];
    const int*   edge_index = (const int*)d_in[1];
    const float* edge_w     = (const float*)d_in[2];
    const float* mask       = (const float*)d_in[3];
    const float* p          = (const float*)d_in[4];
    const float* Wz         = (const float*)d_in[5];
    const float* Uz         = (const float*)d_in[6];
    const float* bz         = (const float*)d_in[7];
    const float* Wr         = (const float*)d_in[8];
    const float* Ur         = (const float*)d_in[9];
    const float* br         = (const float*)d_in[10];
    const float* Wh         = (const float*)d_in[11];
    const float* Uh         = (const float*)d_in[12];
    const float* bh         = (const float*)d_in[13];
    const float* W0         = (const float*)d_in[14];
    float* out = (float*)d_out;

    // MEGA: scores|deg|prep -> scan|select -> WX -> gru(0) -> fill(0), one launch
    mega_kernel<<<MB_TOT, 256>>>(node_embs, p, mask, edge_index, edge_w,
                                 Wz, Uz, Wr, Ur, Wh, Uh, W0, bz, br, bh);

    // P0: gruA(1)+gruB(1) | sgemm(0) | fill(1)
    pipe_kernel<<<64 + SGB + 2500, 256>>>(0, -1, 1, 1, node_embs,
                                          edge_index, edge_w, bz, br, bh, out);
    // P1: gruA(2)+gruB(2) | sgemm(1) | fill(2) | gather(0)
    pipe_kernel<<<64 + SGB + 2500 + 2500, 256>>>(1, 0, 2, 1, node_embs,
                                                 edge_index, edge_w, bz, br, bh, out);
    // P2: gruA(3)+gruB(3) | sgemm(2) | fill(3) | gather(1)
    pipe_kernel<<<64 + SGB + 2500 + 2500, 256>>>(2, 1, 3, 1, node_embs,
                                                 edge_index, edge_w, bz, br, bh, out);
    // P3: sgemm(3) | gather(2)
    pipe_kernel<<<SGB + 2500, 256>>>(3, 2, -1, 0, node_embs,
                                     edge_index, edge_w, bz, br, bh, out);
    gather_only_kernel<<<2500, 256>>>(3, out);
}

// round 15
// speedup vs baseline: 1.4075x; 1.4075x over previous
#include <cuda_runtime.h>
#include <cuda_fp16.h>

#define TT   4
#define NN   20000
#define EE   640000
#define DIN  256
#define DOUT 128
#define MAT  (DIN * DOUT)      // 32768
#define MSQ  (DIN * DIN)       // 65536
#define SLOPE 0.22916666666666666f

typedef unsigned long long ull;

// ---------------- scratch (__device__ globals; no allocation) ----------------
__device__ float  g_scores[TT * NN];
__device__ float  g_xt[TT * MAT];             // per-t [256][128]
__device__ float  g_Wn[(TT + 1) * MAT];       // W0 + evolved weights (fp32)
__device__ __half g_Wh[TT * MAT];             // Wn(t+1) fp16 for the y-GEMM
__device__ __half g_xh[(size_t)TT * NN * DIN];// fp16 copy of node_embs (41 MB)
__device__ float  g_WT[6 * MSQ];              // transposed Wz,Uz,Wr,Ur,Wh,Uh
__device__ float  g_WX[3 * TT * MAT];         // Wz@xt, Wr@xt, Wh@xt per t
__device__ float  g_z[MAT];
__device__ float  g_rW[MAT];
__device__ __half g_y[(size_t)TT * NN * DOUT];
__device__ int    g_deg[TT * NN];
__device__ int    g_off[TT * (NN + 1)];
__device__ int    g_cur[TT * NN];
__device__ int2   g_csr[(size_t)TT * EE];
__device__ int    g_hist[TT * 4096];          // zero-init; re-zeroed in select
// intra-kernel producer/consumer flags (reset every replay in front_kernel)
__device__ int    g_flagWX;                   // 32 when WX(t=0) complete
__device__ int    g_flagA[TT];                // 32 when gruA(t) complete

// ---------------- helpers ----------------
__device__ __forceinline__ unsigned ord_of(float f) {
    unsigned b = __float_as_uint(f);
    return b ^ ((b & 0x80000000u) ? 0xFFFFFFFFu : 0x80000000u);
}
__device__ __forceinline__ float sigmoidf_(float x) {
    return 1.0f / (1.0f + expf(-x));
}
__device__ __forceinline__ float2 upk(ull v) {
    float2 r;
    asm("mov.b64 {%0, %1}, %2;" : "=f"(r.x), "=f"(r.y) : "l"(v));
    return r;
}
__device__ __forceinline__ ull dup2(float a) {
    ull r;
    asm("mov.b64 %0, {%1, %1};" : "=l"(r) : "f"(a));
    return r;
}
__device__ __forceinline__ unsigned smaddr(const void* p) {
    return (unsigned)__cvta_generic_to_shared(p);
}
__device__ __forceinline__ void flag_release(int* f) {
    __threadfence();
    __syncthreads();
    if (threadIdx.x == 0) atomicAdd(f, 1);
}
__device__ __forceinline__ void flag_wait(const int* f, int target) {
    if (threadIdx.x == 0) {
        while (*(volatile const int*)f < target) __nanosleep(1024);
    }
    __syncthreads();
    __threadfence();
}

// ================= L1: front = scores+hist+fp16copy | deg | prep+flag-reset ==
#define FB_SCORES 10000
#define FB_DEG    10000
#define FB_PREP   1664
#define FB_TOTAL  (FB_SCORES + FB_DEG + FB_PREP)

__global__ void front_kernel(const float* __restrict__ embs,
                             const float* __restrict__ p,
                             const float* __restrict__ mask,
                             const int* __restrict__ ei,
                             const float* __restrict__ Wz, const float* __restrict__ Uz,
                             const float* __restrict__ Wr, const float* __restrict__ Ur,
                             const float* __restrict__ Wh, const float* __restrict__ Uh,
                             const float* __restrict__ W0) {
    int b = blockIdx.x;
    int tid = threadIdx.x;
    if (b < FB_SCORES) {
        __shared__ float sp[DIN];
        sp[tid] = p[tid];
        __syncthreads();
        int t = b / 2500;
        int warp = tid >> 5, lane = tid & 31;
        int n = (b % 2500) * 8 + warp;
        const float* xr = embs + ((size_t)t * NN + n) * DIN;
        float4 x0 = *(const float4*)&xr[lane * 4];
        float4 x1 = *(const float4*)&xr[128 + lane * 4];
        __half* xh = g_xh + ((size_t)t * NN + n) * DIN;
        *(__half2*)&xh[lane * 4]           = __floats2half2_rn(x0.x, x0.y);
        *(__half2*)&xh[lane * 4 + 2]       = __floats2half2_rn(x0.z, x0.w);
        *(__half2*)&xh[128 + lane * 4]     = __floats2half2_rn(x1.x, x1.y);
        *(__half2*)&xh[128 + lane * 4 + 2] = __floats2half2_rn(x1.z, x1.w);
        float4 p0 = *(const float4*)&sp[lane * 4];
        float4 p1 = *(const float4*)&sp[128 + lane * 4];
        float s = x0.x * p0.x + x0.y * p0.y + x0.z * p0.z + x0.w * p0.w
                + x1.x * p1.x + x1.y * p1.y + x1.z * p1.z + x1.w * p1.w;
        float q = p0.x * p0.x + p0.y * p0.y + p0.z * p0.z + p0.w * p0.w
                + p1.x * p1.x + p1.y * p1.y + p1.z * p1.z + p1.w * p1.w;
#pragma unroll
        for (int o = 16; o > 0; o >>= 1) {
            s += __shfl_down_sync(0xFFFFFFFFu, s, o);
            q += __shfl_down_sync(0xFFFFFFFFu, q, o);
        }
        if (lane == 0) {
            float sc = s * rsqrtf(q) + mask[t * NN + n];
            g_scores[t * NN + n] = sc;
            atomicAdd(&g_hist[t * 4096 + (ord_of(sc) >> 20)], 1);
        }
    } else if (b < FB_SCORES + FB_DEG) {
        int idx = b - FB_SCORES;
        int t = idx / 2500;
        int e = (idx % 2500) * 256 + tid;
        const int* dst = ei + (size_t)t * 2 * EE;
        atomicAdd(&g_deg[t * NN + dst[e]], 1);
    } else {
        if (b == FB_SCORES + FB_DEG) {   // reset flags each replay
            if (tid == 0) g_flagWX = 0;
            else if (tid < 1 + TT) g_flagA[tid - 1] = 0;
        }
        int idx = (b - FB_SCORES - FB_DEG) * 256 + tid;
        const float* srcs[6] = {Wz, Uz, Wr, Ur, Wh, Uh};
        if (idx < 6 * MSQ) {
            int m = idx >> 16;
            int e = idx & 0xFFFF;
            int k = e >> 8, i = e & 255;
            g_WT[idx] = srcs[m][i * DIN + k];
        } else {
            int e = idx - 6 * MSQ;
            g_Wn[e] = W0[e];
        }
    }
}

// ================= L2: mid2s = select+xt (blocks 0-3) | scan (blocks 4-7) =====
__device__ void do_scan(int t) {
    __shared__ int part[1024];
    int tid = threadIdx.x;
    int* deg = g_deg + t * NN;
    int* off = g_off + t * (NN + 1);
    int* cur = g_cur + t * NN;
    int base = tid * 20;
    int loc[20];
    int sum = 0;
#pragma unroll
    for (int i = 0; i < 20; i++) {
        int n = base + i;
        int d = (n < NN) ? deg[n] : 0;
        if (n < NN) deg[n] = 0;
        loc[i] = sum;
        sum += d;
    }
    part[tid] = sum;
    __syncthreads();
    for (int o = 1; o < 1024; o <<= 1) {
        int v = (tid >= o) ? part[tid - o] : 0;
        __syncthreads();
        part[tid] += v;
        __syncthreads();
    }
    int myoff = tid ? part[tid - 1] : 0;
#pragma unroll
    for (int i = 0; i < 20; i++) {
        int n = base + i;
        if (n <= NN) {
            int o = myoff + loc[i];
            off[n] = o;
            if (n < NN) cur[n] = o;
        }
    }
}

__device__ void do_select(int t, const float* __restrict__ embs) {
    int tid = threadIdx.x;   // 1024
    __shared__ int part[1024];
    __shared__ int sB, sAbove;
    __shared__ unsigned cnt_gt, cnt_cand;
    __shared__ unsigned sel_ord[DOUT];
    __shared__ int sel_idx[DOUT];
    __shared__ unsigned cand_ord[512];
    __shared__ int cand_idx[512];
    __shared__ int sh_idx[DOUT];
    __shared__ float sh_tanh[DOUT];

    const float* scores = g_scores + t * NN;
    int* hist = g_hist + t * 4096;

    int cnt[4];
    int s = 0;
#pragma unroll
    for (int j = 0; j < 4; j++) {
        int bin = 4095 - (tid * 4 + j);
        cnt[j] = hist[bin];
        s += cnt[j];
    }
    part[tid] = s;
    if (tid == 0) { cnt_gt = 0; cnt_cand = 0; }
    __syncthreads();
    for (int o = 1; o < 1024; o <<= 1) {
        int v = (tid >= o) ? part[tid - o] : 0;
        __syncthreads();
        part[tid] += v;
        __syncthreads();
    }
    int c = tid ? part[tid - 1] : 0;
#pragma unroll
    for (int j = 0; j < 4; j++) {
        int bin = 4095 - (tid * 4 + j);
        if (c < DOUT && c + cnt[j] >= DOUT) { sB = bin; sAbove = c; }
        c += cnt[j];
    }
    __syncthreads();
#pragma unroll
    for (int j = 0; j < 4; j++) hist[4095 - (tid * 4 + j)] = 0;
    int B = sB, above = sAbove, kneed = DOUT - above;

    for (int n = tid; n < NN; n += 1024) {
        unsigned ord = ord_of(scores[n]);
        int bucket = ord >> 20;
        if (bucket > B) {
            unsigned pos = atomicAdd(&cnt_gt, 1u);
            sel_ord[pos] = ord; sel_idx[pos] = n;
        } else if (bucket == B) {
            unsigned pos = atomicAdd(&cnt_cand, 1u);
            if (pos < 512) { cand_ord[pos] = ord; cand_idx[pos] = n; }
        }
    }
    __syncthreads();
    int nc = (int)cnt_cand; if (nc > 512) nc = 512;
    for (int ci = tid; ci < nc; ci += 1024) {
        unsigned mo = cand_ord[ci];
        int mi = cand_idx[ci];
        int r = 0;
        for (int j = 0; j < nc; j++) {
            unsigned o = cand_ord[j];
            r += (o > mo) || (o == mo && cand_idx[j] < mi);
        }
        if (r < kneed) { sel_ord[above + r] = mo; sel_idx[above + r] = mi; }
    }
    __syncthreads();
    if (tid < DOUT) {
        unsigned mo = sel_ord[tid];
        int mi = sel_idx[tid];
        int r = 0;
#pragma unroll 4
        for (int i = 0; i < DOUT; i++) {
            unsigned o = sel_ord[i];
            r += (o > mo) || (o == mo && sel_idx[i] < mi);
        }
        sh_idx[r] = mi;
        sh_tanh[r] = tanhf(scores[mi]);
    }
    __syncthreads();
    float* xt = g_xt + t * MAT;
    for (int e = tid; e < MAT; e += 1024) {
        int j = e >> 8;
        int d = e & 255;
        xt[d * DOUT + j] = embs[((size_t)t * NN + sh_idx[j]) * DIN + d] * sh_tanh[j];
    }
}

__global__ void mid2s_kernel(const float* __restrict__ embs) {
    if (blockIdx.x < TT) do_select(blockIdx.x, embs);
    else                 do_scan(blockIdx.x - TT);
}

// ===== small GEMM: 8x128 tile, K=256, up to 3 A-mats sharing B (256 thr) ======
#define KT 32
template <int NMAT>
__device__ __forceinline__ void gemmR8(const float* __restrict__ AT0,
                                       const float* __restrict__ AT1,
                                       const float* __restrict__ AT2,
                                       const float* __restrict__ Bmat,
                                       int i0, ull a0[2], ull a1[2], ull a2[2],
                                       char* sm) {
    float (*Bs)[128] = (float(*)[128])sm;                // 16 KB
    float (*As)[8]   = (float(*)[8])(sm + KT * 128 * 4); // NMAT*32*8 floats
    int tid = threadIdx.x;           // 256
    int ti = tid & 7, tj = tid >> 3;
    int brow = tid >> 5, bcol = (tid & 31) * 4;
    int akk = tid >> 3, aii = tid & 7;

    float4 pb[4];
    float pa0, pa1, pa2;
#pragma unroll
    for (int l = 0; l < 4; l++)
        pb[l] = *(const float4*)&Bmat[(brow + 8 * l) * 128 + bcol];
    pa0 = AT0[akk * DIN + i0 + aii];
    if (NMAT > 1) pa1 = AT1[akk * DIN + i0 + aii];
    if (NMAT > 2) pa2 = AT2[akk * DIN + i0 + aii];

    for (int k0 = 0; k0 < DIN; k0 += KT) {
#pragma unroll
        for (int l = 0; l < 4; l++)
            *(float4*)&Bs[brow + 8 * l][bcol] = pb[l];
        As[0 * KT + akk][aii] = pa0;
        if (NMAT > 1) As[1 * KT + akk][aii] = pa1;
        if (NMAT > 2) As[2 * KT + akk][aii] = pa2;
        __syncthreads();
        int kn = k0 + KT;
        if (kn < DIN) {
#pragma unroll
            for (int l = 0; l < 4; l++)
                pb[l] = *(const float4*)&Bmat[(kn + brow + 8 * l) * 128 + bcol];
            pa0 = AT0[(kn + akk) * DIN + i0 + aii];
            if (NMAT > 1) pa1 = AT1[(kn + akk) * DIN + i0 + aii];
            if (NMAT > 2) pa2 = AT2[(kn + akk) * DIN + i0 + aii];
        }
#pragma unroll
        for (int kk = 0; kk < KT; kk++) {
            ull b0 = *(const ull*)&Bs[kk][tj * 4 + 0];
            ull b1 = *(const ull*)&Bs[kk][tj * 4 + 2];
            {
                ull av = dup2(As[0 * KT + kk][ti]);
                asm("fma.rn.f32x2 %0, %1, %2, %0;" : "+l"(a0[0]) : "l"(av), "l"(b0));
                asm("fma.rn.f32x2 %0, %1, %2, %0;" : "+l"(a0[1]) : "l"(av), "l"(b1));
            }
            if (NMAT > 1) {
                ull av = dup2(As[1 * KT + kk][ti]);
                asm("fma.rn.f32x2 %0, %1, %2, %0;" : "+l"(a1[0]) : "l"(av), "l"(b0));
                asm("fma.rn.f32x2 %0, %1, %2, %0;" : "+l"(a1[1]) : "l"(av), "l"(b1));
            }
            if (NMAT > 2) {
                ull av = dup2(As[2 * KT + kk][ti]);
                asm("fma.rn.f32x2 %0, %1, %2, %0;" : "+l"(a2[0]) : "l"(av), "l"(b0));
                asm("fma.rn.f32x2 %0, %1, %2, %0;" : "+l"(a2[1]) : "l"(av), "l"(b1));
            }
        }
        __syncthreads();
    }
}

// ---- gruA (32 blocks): z = sig(WXz+Uz@W+bz), r = sig(WXr+Ur@W+br), rW = r*W --
__device__ __forceinline__ void dev_gruA(int t, int bx,
                                         const float* __restrict__ bz,
                                         const float* __restrict__ br,
                                         char* sm, bool wait_wx) {
    int i0 = bx * 8;
    ull a0[2] = {0, 0}, a1[2] = {0, 0};
    gemmR8<2>(g_WT + 1 * MSQ, g_WT + 3 * MSQ, (const float*)0,
              g_Wn + t * MAT, i0, a0, a1, a0, sm);
    if (wait_wx) flag_wait(&g_flagWX, 32);
    int ti = threadIdx.x & 7, tj = threadIdx.x >> 3;
    int row = i0 + ti, col = tj * 4;
    const float* WXz = g_WX + (0 * TT + t) * MAT;
    const float* WXr = g_WX + (1 * TT + t) * MAT;
    const float* Wt  = g_Wn + t * MAT;
#pragma unroll
    for (int j = 0; j < 2; j++) {
        int o = row * DOUT + col + 2 * j;
        float2 az = upk(a0[j]), ar = upk(a1[j]);
        float2 xz = *(const float2*)&WXz[o];
        float2 xr = *(const float2*)&WXr[o];
        float2 vz = *(const float2*)&bz[o];
        float2 vr = *(const float2*)&br[o];
        float2 wv = *(const float2*)&Wt[o];
        float2 z2, rw2;
        z2.x = sigmoidf_(az.x + xz.x + vz.x);
        z2.y = sigmoidf_(az.y + xz.y + vz.y);
        rw2.x = sigmoidf_(ar.x + xr.x + vr.x) * wv.x;
        rw2.y = sigmoidf_(ar.y + xr.y + vr.y) * wv.y;
        *(float2*)&g_z[o] = z2;
        *(float2*)&g_rW[o] = rw2;
    }
    flag_release(&g_flagA[t]);
}

// ---- gruB (32 blocks): h = tanh(WXh+Uh@rW+bh); Wn_{t+1} = W + z*(h-W) -------
__device__ __forceinline__ void dev_gruB(int t, int bx,
                                         const float* __restrict__ bh, char* sm) {
    flag_wait(&g_flagA[t], 32);
    int i0 = bx * 8;
    ull a0[2] = {0, 0};
    gemmR8<1>(g_WT + 5 * MSQ, (const float*)0, (const float*)0,
              g_rW, i0, a0, a0, a0, sm);
    int ti = threadIdx.x & 7, tj = threadIdx.x >> 3;
    int row = i0 + ti, col = tj * 4;
    const float* WXh = g_WX + (2 * TT + t) * MAT;
    const float* Wt  = g_Wn + t * MAT;
    float* Wnx = g_Wn + (t + 1) * MAT;
    __half* Whx = g_Wh + t * MAT;
#pragma unroll
    for (int j = 0; j < 2; j++) {
        int o = row * DOUT + col + 2 * j;
        float2 ah = upk(a0[j]);
        float2 xh = *(const float2*)&WXh[o];
        float2 vh = *(const float2*)&bh[o];
        float2 wv = *(const float2*)&Wt[o];
        float2 z2 = *(const float2*)&g_z[o];
        float hx = tanhf(ah.x + xh.x + vh.x);
        float hy = tanhf(ah.y + xh.y + vh.y);
        float2 wn;
        wn.x = wv.x + z2.x * (hx - wv.x);
        wn.y = wv.y + z2.y * (hy - wv.y);
        *(float2*)&Wnx[o] = wn;
        *(__half2*)&Whx[o] = __float22half2_rn(wn);
    }
}

// ---- CSR fill body (2500 blocks per t) ---------------------------------------
__device__ __forceinline__ void dev_fill(int t, int bx,
                                         const int* __restrict__ ei,
                                         const float* __restrict__ w) {
    int e = bx * 256 + threadIdx.x;
    const int* dst = ei + (size_t)t * 2 * EE;
    const int* src = dst + EE;
    int d = dst[e];
    int pos = atomicAdd(&g_cur[t * NN + d], 1);
    g_csr[(size_t)t * EE + pos] = make_int2(src[e], __float_as_int(w[(size_t)t * EE + e]));
}

// ================= WXG: WX GEMMs(128) | gruA0(32) | gruB0(32) | fill(0) ======
#define WXG_SMEM (KT * 128 * 4 + 3 * KT * 8 * 4)
__global__ void wxg_kernel(const int* __restrict__ ei, const float* __restrict__ w,
                           const float* __restrict__ bz, const float* __restrict__ br,
                           const float* __restrict__ bh) {
    __shared__ __align__(16) char sm[WXG_SMEM];
    int b = blockIdx.x;
    if (b < 128) {
        int t = b >> 5, i0 = (b & 31) * 8;
        ull a0[2] = {0, 0}, a1[2] = {0, 0}, a2[2] = {0, 0};
        gemmR8<3>(g_WT + 0 * MSQ, g_WT + 2 * MSQ, g_WT + 4 * MSQ,
                  g_xt + t * MAT, i0, a0, a1, a2, sm);
        int ti = threadIdx.x & 7, tj = threadIdx.x >> 3;
        int base = (i0 + ti) * DOUT + tj * 4;
#pragma unroll
        for (int j = 0; j < 2; j++) {
            *(ull*)&g_WX[(0 * TT + t) * MAT + base + 2 * j] = a0[j];
            *(ull*)&g_WX[(1 * TT + t) * MAT + base + 2 * j] = a1[j];
            *(ull*)&g_WX[(2 * TT + t) * MAT + base + 2 * j] = a2[j];
        }
        if (t == 0) flag_release(&g_flagWX);
    } else if (b < 160) {
        dev_gruA(0, b - 128, bz, br, sm, true);
    } else if (b < 192) {
        dev_gruB(0, b - 160, bh, sm);
    } else {
        dev_fill(0, b - 192, ei, w);
    }
}

// ================= tensor-core sgemm: y_t = xh_t @ Wh_t (fp16 in, fp32 acc) ===
#define BM 64
#define BN 128
#define SGB ((NN + BM - 1) / BM)   // 313
#define ASTRIDE 40
#define BSTRIDE 136

__device__ __forceinline__ void dev_sgemm(int t, int bx, char* sm) {
    __half* Ah = (__half*)sm;                       // [64][ASTRIDE]
    __half* Bh = (__half*)(sm + 64 * ASTRIDE * 2);  // [32][BSTRIDE]
    const __half* A = g_xh + (size_t)t * NN * DIN;
    const __half* B = g_Wh + t * MAT;
    __half* C = g_y + (size_t)t * NN * DOUT;
    int tid = threadIdx.x, lane = tid & 31, wid = tid >> 5;
    int wm = wid >> 2, wq = wid & 3;
    int bm = bx * BM;

    float c[2][4][4];
#pragma unroll
    for (int ma = 0; ma < 2; ma++)
#pragma unroll
        for (int na = 0; na < 4; na++)
#pragma unroll
            for (int i = 0; i < 4; i++) c[ma][na][i] = 0.0f;

    int arow = tid >> 2, acol = (tid & 3) * 8;
    int agr = bm + arow;
    uint4 zero4 = make_uint4(0, 0, 0, 0);

    for (int k0 = 0; k0 < DIN; k0 += 32) {
        uint4 av = (agr < NN) ? *(const uint4*)&A[(size_t)agr * DIN + k0 + acol] : zero4;
        *(uint4*)&Ah[arow * ASTRIDE + acol] = av;
#pragma unroll
        for (int pp = 0; pp < 2; pp++) {
            int q = tid + pp * 256;
            int brr = q >> 4, bcc = (q & 15) * 8;
            *(uint4*)&Bh[brr * BSTRIDE + bcc] = *(const uint4*)&B[(k0 + brr) * BN + bcc];
        }
        __syncthreads();
#pragma unroll
        for (int ks = 0; ks < 32; ks += 16) {
            unsigned bf[4][2];
#pragma unroll
            for (int na = 0; na < 4; na++) {
                int r = ks + (lane & 15);
                unsigned ad = smaddr(&Bh[r * BSTRIDE + wq * 32 + na * 8]);
                asm volatile("ldmatrix.sync.aligned.m8n8.x2.trans.shared.b16 {%0,%1}, [%2];"
                             : "=r"(bf[na][0]), "=r"(bf[na][1]) : "r"(ad));
            }
#pragma unroll
            for (int ma = 0; ma < 2; ma++) {
                int mr = wm * 32 + ma * 16 + (lane & 15);
                int kc = ks + ((lane >> 4) << 3);
                unsigned ad = smaddr(&Ah[mr * ASTRIDE + kc]);
                unsigned a0, a1, a2, a3;
                asm volatile("ldmatrix.sync.aligned.m8n8.x4.shared.b16 {%0,%1,%2,%3}, [%4];"
                             : "=r"(a0), "=r"(a1), "=r"(a2), "=r"(a3) : "r"(ad));
#pragma unroll
                for (int na = 0; na < 4; na++) {
                    asm volatile(
                        "mma.sync.aligned.m16n8k16.row.col.f32.f16.f16.f32 "
                        "{%0,%1,%2,%3}, {%4,%5,%6,%7}, {%8,%9}, {%0,%1,%2,%3};"
                        : "+f"(c[ma][na][0]), "+f"(c[ma][na][1]),
                          "+f"(c[ma][na][2]), "+f"(c[ma][na][3])
                        : "r"(a0), "r"(a1), "r"(a2), "r"(a3),
                          "r"(bf[na][0]), "r"(bf[na][1]));
                }
            }
        }
        __syncthreads();
    }
#pragma unroll
    for (int ma = 0; ma < 2; ma++) {
        int row0 = bm + wm * 32 + ma * 16 + (lane >> 2);
#pragma unroll
        for (int na = 0; na < 4; na++) {
            int col = wq * 32 + na * 8 + (lane & 3) * 2;
            if (row0 < NN)
                *(__half2*)&C[(size_t)row0 * DOUT + col] =
                    __floats2half2_rn(c[ma][na][0], c[ma][na][1]);
            if (row0 + 8 < NN)
                *(__half2*)&C[(size_t)(row0 + 8) * DOUT + col] =
                    __floats2half2_rn(c[ma][na][2], c[ma][na][3]);
        }
    }
}

// ---- gather: 8 edge-rows in flight per warp (y(t) produced in prior launch) --
__device__ __forceinline__ void dev_gather(int t, int bx, float* __restrict__ out) {
    int node = bx * 8 + (threadIdx.x >> 5);
    int lane = threadIdx.x & 31;
    const int* off = g_off + t * (NN + 1);
    const int2* csr = g_csr + (size_t)t * EE;
    const __half* y = g_y + (size_t)t * NN * DOUT;
    int beg = off[node], end = off[node + 1];
    float4 acc = make_float4(0.f, 0.f, 0.f, 0.f);
    int e = beg;
    for (; e + 8 <= end; e += 8) {
        int2 cc[8];
        uint2 rr[8];
#pragma unroll
        for (int u = 0; u < 8; u++) cc[u] = csr[e + u];
#pragma unroll
        for (int u = 0; u < 8; u++)
            rr[u] = *(const uint2*)&y[(size_t)cc[u].x * DOUT + lane * 4];
#pragma unroll
        for (int u = 0; u < 8; u++) {
            float wv = __int_as_float(cc[u].y);
            float2 av = __half22float2(*(__half2*)&rr[u].x);
            float2 bv = __half22float2(*(__half2*)&rr[u].y);
            acc.x += wv * av.x;
            acc.y += wv * av.y;
            acc.z += wv * bv.x;
            acc.w += wv * bv.y;
        }
    }
    for (; e < end; e++) {
        int2 c0 = csr[e];
        float w0 = __int_as_float(c0.y);
        uint2 r0 = *(const uint2*)&y[(size_t)c0.x * DOUT + lane * 4];
        float2 a0 = __half22float2(*(__half2*)&r0.x), b0 = __half22float2(*(__half2*)&r0.y);
        acc.x += w0 * a0.x; acc.y += w0 * a0.y; acc.z += w0 * b0.x; acc.w += w0 * b0.y;
    }
    acc.x = (acc.x >= 0.f) ? acc.x : SLOPE * acc.x;
    acc.y = (acc.y >= 0.f) ? acc.y : SLOPE * acc.y;
    acc.z = (acc.z >= 0.f) ? acc.z : SLOPE * acc.z;
    acc.w = (acc.w >= 0.f) ? acc.w : SLOPE * acc.w;
    *(float4*)&out[((size_t)t * NN + node) * DOUT + lane * 4] = acc;
}

// ==== pipe P(t): gruA(t+1)|gruB(t+1)(spin)|sgemm(t)|fill(t+1)|gather(t-1) =====
#define PIPE_SMEM (KT * 128 * 4 + 2 * KT * 8 * 4)   // 18432 >= sgemm smem 13824
__global__ __launch_bounds__(256, 3)
void pipe_kernel(int t_sg, int t_ga, int t_fill, int has_gru,
                 const int* __restrict__ ei, const float* __restrict__ w,
                 const float* __restrict__ bz, const float* __restrict__ br,
                 const float* __restrict__ bh,
                 float* __restrict__ out) {
    __shared__ __align__(16) char sm[PIPE_SMEM];
    int b = blockIdx.x;
    if (has_gru) {
        if (b < 32) { dev_gruA(t_sg + 1, b, bz, br, sm, false); return; }
        if (b < 64) { dev_gruB(t_sg + 1, b - 32, bh, sm); return; }
        b -= 64;
    }
    if (b < SGB) { dev_sgemm(t_sg, b, sm); return; }
    b -= SGB;
    if (t_fill >= 0) {
        if (b < 2500) { dev_fill(t_fill, b, ei, w); return; }
        b -= 2500;
    }
    dev_gather(t_ga, b, out);
}

__global__ void gather_only_kernel(int t, float* __restrict__ out) {
    dev_gather(t, blockIdx.x, out);
}

// ---------------- launcher ----------------
extern "C" void kernel_launch(void* const* d_in, const int* in_sizes, int n_in,
                              void* d_out, int out_size) {
    const float* node_embs  = (const float*)d_in[0];
    const int*   edge_index = (const int*)d_in[1];
    const float* edge_w     = (const float*)d_in[2];
    const float* mask       = (const float*)d_in[3];
    const float* p          = (const float*)d_in[4];
    const float* Wz         = (const float*)d_in[5];
    const float* Uz         = (const float*)d_in[6];
    const float* bz         = (const float*)d_in[7];
    const float* Wr         = (const float*)d_in[8];
    const float* Ur         = (const float*)d_in[9];
    const float* br         = (const float*)d_in[10];
    const float* Wh         = (const float*)d_in[11];
    const float* Uh         = (const float*)d_in[12];
    const float* bh         = (const float*)d_in[13];
    const float* W0         = (const float*)d_in[14];
    float* out = (float*)d_out;

    front_kernel<<<FB_TOTAL, 256>>>(node_embs, p, mask, edge_index,
                                    Wz, Uz, Wr, Ur, Wh, Uh, W0);
    mid2s_kernel<<<2 * TT, 1024>>>(node_embs);
    wxg_kernel<<<192 + 2500, 256>>>(edge_index, edge_w, bz, br, bh);

    // P0: gruA(1)+gruB(1) | sgemm(0) | fill(1)
    pipe_kernel<<<64 + SGB + 2500, 256>>>(0, -1, 1, 1, edge_index, edge_w,
                                          bz, br, bh, out);
    // P1: gruA(2)+gruB(2) | sgemm(1) | fill(2) | gather(0)
    pipe_kernel<<<64 + SGB + 2500 + 2500, 256>>>(1, 0, 2, 1, edge_index, edge_w,
                                                 bz, br, bh, out);
    // P2: gruA(3)+gruB(3) | sgemm(2) | fill(3) | gather(1)
    pipe_kernel<<<64 + SGB + 2500 + 2500, 256>>>(2, 1, 3, 1, edge_index, edge_w,
                                                 bz, br, bh, out);
    // P3: sgemm(3) | gather(2)
    pipe_kernel<<<SGB + 2500, 256>>>(3, 2, -1, 0, edge_index, edge_w,
                                     bz, br, bh, out);
    gather_only_kernel<<<2500, 256>>>(3, out);
}

// round 16
// speedup vs baseline: 1.4277x; 1.0143x over previous
#include <cuda_runtime.h>
#include <cuda_fp16.h>

#define TT   4
#define NN   20000
#define EE   640000
#define DIN  256
#define DOUT 128
#define MAT  (DIN * DOUT)      // 32768
#define MSQ  (DIN * DIN)       // 65536
#define SLOPE 0.22916666666666666f

typedef unsigned long long ull;

// ---------------- scratch (__device__ globals; no allocation) ----------------
__device__ float  g_scores[TT * NN];
__device__ float  g_xt[TT * MAT];             // per-t [256][128]
__device__ float  g_Wn[(TT + 1) * MAT];       // W0 + evolved weights (fp32)
__device__ __half g_Wh[TT * MAT];             // Wn(t+1) fp16 for the y-GEMM
__device__ __half g_xh[(size_t)TT * NN * DIN];// fp16 copy of node_embs (41 MB)
__device__ float  g_WT[6 * MSQ];              // transposed Wz,Uz,Wr,Ur,Wh,Uh
__device__ float  g_WX[3 * TT * MAT];         // Wz@xt, Wr@xt, Wh@xt per t
__device__ float  g_z[MAT];
__device__ float  g_rW[MAT];
__device__ __half g_y[(size_t)TT * NN * DOUT];
__device__ int    g_deg[TT * NN];
__device__ int    g_off[TT * (NN + 1)];
__device__ int    g_cur[TT * NN];
__device__ int2   g_csr[(size_t)TT * EE];
__device__ int    g_hist[TT * 4096];          // zero-init; re-zeroed in select
// intra-kernel producer/consumer flags (reset every replay in front_kernel)
__device__ int    g_flagWX;                   // 32 when WX(t=0) complete
__device__ int    g_flagA[TT];                // 32 when gruA(t) complete

// ---------------- helpers ----------------
__device__ __forceinline__ unsigned ord_of(float f) {
    unsigned b = __float_as_uint(f);
    return b ^ ((b & 0x80000000u) ? 0xFFFFFFFFu : 0x80000000u);
}
__device__ __forceinline__ float sigmoidf_(float x) {
    return 1.0f / (1.0f + expf(-x));
}
__device__ __forceinline__ float2 upk(ull v) {
    float2 r;
    asm("mov.b64 {%0, %1}, %2;" : "=f"(r.x), "=f"(r.y) : "l"(v));
    return r;
}
__device__ __forceinline__ ull dup2(float a) {
    ull r;
    asm("mov.b64 %0, {%1, %1};" : "=l"(r) : "f"(a));
    return r;
}
__device__ __forceinline__ unsigned smaddr(const void* p) {
    return (unsigned)__cvta_generic_to_shared(p);
}
__device__ __forceinline__ void flag_release(int* f) {
    __threadfence();
    __syncthreads();
    if (threadIdx.x == 0) atomicAdd(f, 1);
}
__device__ __forceinline__ void flag_wait(const int* f, int target) {
    if (threadIdx.x == 0) {
        while (*(volatile const int*)f < target) __nanosleep(1024);
    }
    __syncthreads();
    __threadfence();
}

// ================= L1: front = scores+hist+fp16copy | deg | prep+flag-reset ==
#define FB_SCORES 10000
#define FB_DEG    10000
#define FB_PREP   1664
#define FB_TOTAL  (FB_SCORES + FB_DEG + FB_PREP)

__global__ void front_kernel(const float* __restrict__ embs,
                             const float* __restrict__ p,
                             const float* __restrict__ mask,
                             const int* __restrict__ ei,
                             const float* __restrict__ Wz, const float* __restrict__ Uz,
                             const float* __restrict__ Wr, const float* __restrict__ Ur,
                             const float* __restrict__ Wh, const float* __restrict__ Uh,
                             const float* __restrict__ W0) {
    int b = blockIdx.x;
    int tid = threadIdx.x;
    if (b < FB_SCORES) {
        __shared__ float sp[DIN];
        sp[tid] = p[tid];
        __syncthreads();
        int t = b / 2500;
        int warp = tid >> 5, lane = tid & 31;
        int n = (b % 2500) * 8 + warp;
        const float* xr = embs + ((size_t)t * NN + n) * DIN;
        float4 x0 = *(const float4*)&xr[lane * 4];
        float4 x1 = *(const float4*)&xr[128 + lane * 4];
        __half* xh = g_xh + ((size_t)t * NN + n) * DIN;
        *(__half2*)&xh[lane * 4]           = __floats2half2_rn(x0.x, x0.y);
        *(__half2*)&xh[lane * 4 + 2]       = __floats2half2_rn(x0.z, x0.w);
        *(__half2*)&xh[128 + lane * 4]     = __floats2half2_rn(x1.x, x1.y);
        *(__half2*)&xh[128 + lane * 4 + 2] = __floats2half2_rn(x1.z, x1.w);
        float4 p0 = *(const float4*)&sp[lane * 4];
        float4 p1 = *(const float4*)&sp[128 + lane * 4];
        float s = x0.x * p0.x + x0.y * p0.y + x0.z * p0.z + x0.w * p0.w
                + x1.x * p1.x + x1.y * p1.y + x1.z * p1.z + x1.w * p1.w;
        float q = p0.x * p0.x + p0.y * p0.y + p0.z * p0.z + p0.w * p0.w
                + p1.x * p1.x + p1.y * p1.y + p1.z * p1.z + p1.w * p1.w;
#pragma unroll
        for (int o = 16; o > 0; o >>= 1) {
            s += __shfl_down_sync(0xFFFFFFFFu, s, o);
            q += __shfl_down_sync(0xFFFFFFFFu, q, o);
        }
        if (lane == 0) {
            float sc = s * rsqrtf(q) + mask[t * NN + n];
            g_scores[t * NN + n] = sc;
            atomicAdd(&g_hist[t * 4096 + (ord_of(sc) >> 20)], 1);
        }
    } else if (b < FB_SCORES + FB_DEG) {
        int idx = b - FB_SCORES;
        int t = idx / 2500;
        int e = (idx % 2500) * 256 + tid;
        const int* dst = ei + (size_t)t * 2 * EE;
        atomicAdd(&g_deg[t * NN + dst[e]], 1);
    } else {
        if (b == FB_SCORES + FB_DEG) {   // reset flags each replay
            if (tid == 0) g_flagWX = 0;
            else if (tid < 1 + TT) g_flagA[tid - 1] = 0;
        }
        int idx = (b - FB_SCORES - FB_DEG) * 256 + tid;
        const float* srcs[6] = {Wz, Uz, Wr, Ur, Wh, Uh};
        if (idx < 6 * MSQ) {
            int m = idx >> 16;
            int e = idx & 0xFFFF;
            int k = e >> 8, i = e & 255;
            g_WT[idx] = srcs[m][i * DIN + k];
        } else {
            int e = idx - 6 * MSQ;
            g_Wn[e] = W0[e];
        }
    }
}

// ================= L2: mid2s = select+xt (blocks 0-3) | scan (blocks 4-7) =====
__device__ void do_scan(int t) {
    __shared__ int part[1024];
    int tid = threadIdx.x;
    int* deg = g_deg + t * NN;
    int* off = g_off + t * (NN + 1);
    int* cur = g_cur + t * NN;
    int base = tid * 20;
    int loc[20];
    int sum = 0;
#pragma unroll
    for (int i = 0; i < 20; i++) {
        int n = base + i;
        int d = (n < NN) ? deg[n] : 0;
        if (n < NN) deg[n] = 0;
        loc[i] = sum;
        sum += d;
    }
    part[tid] = sum;
    __syncthreads();
    for (int o = 1; o < 1024; o <<= 1) {
        int v = (tid >= o) ? part[tid - o] : 0;
        __syncthreads();
        part[tid] += v;
        __syncthreads();
    }
    int myoff = tid ? part[tid - 1] : 0;
#pragma unroll
    for (int i = 0; i < 20; i++) {
        int n = base + i;
        if (n <= NN) {
            int o = myoff + loc[i];
            off[n] = o;
            if (n < NN) cur[n] = o;
        }
    }
}

__device__ void do_select(int t, const float* __restrict__ embs) {
    int tid = threadIdx.x;   // 1024
    __shared__ int part[1024];
    __shared__ int sB, sAbove;
    __shared__ unsigned cnt_gt, cnt_cand;
    __shared__ unsigned sel_ord[DOUT];
    __shared__ int sel_idx[DOUT];
    __shared__ unsigned cand_ord[512];
    __shared__ int cand_idx[512];
    __shared__ int sh_idx[DOUT];
    __shared__ float sh_tanh[DOUT];

    const float* scores = g_scores + t * NN;
    int* hist = g_hist + t * 4096;

    int cnt[4];
    int s = 0;
#pragma unroll
    for (int j = 0; j < 4; j++) {
        int bin = 4095 - (tid * 4 + j);
        cnt[j] = hist[bin];
        s += cnt[j];
    }
    part[tid] = s;
    if (tid == 0) { cnt_gt = 0; cnt_cand = 0; }
    __syncthreads();
    for (int o = 1; o < 1024; o <<= 1) {
        int v = (tid >= o) ? part[tid - o] : 0;
        __syncthreads();
        part[tid] += v;
        __syncthreads();
    }
    int c = tid ? part[tid - 1] : 0;
#pragma unroll
    for (int j = 0; j < 4; j++) {
        int bin = 4095 - (tid * 4 + j);
        if (c < DOUT && c + cnt[j] >= DOUT) { sB = bin; sAbove = c; }
        c += cnt[j];
    }
    __syncthreads();
#pragma unroll
    for (int j = 0; j < 4; j++) hist[4095 - (tid * 4 + j)] = 0;
    int B = sB, above = sAbove, kneed = DOUT - above;

    for (int n = tid; n < NN; n += 1024) {
        unsigned ord = ord_of(scores[n]);
        int bucket = ord >> 20;
        if (bucket > B) {
            unsigned pos = atomicAdd(&cnt_gt, 1u);
            sel_ord[pos] = ord; sel_idx[pos] = n;
        } else if (bucket == B) {
            unsigned pos = atomicAdd(&cnt_cand, 1u);
            if (pos < 512) { cand_ord[pos] = ord; cand_idx[pos] = n; }
        }
    }
    __syncthreads();
    int nc = (int)cnt_cand; if (nc > 512) nc = 512;
    for (int ci = tid; ci < nc; ci += 1024) {
        unsigned mo = cand_ord[ci];
        int mi = cand_idx[ci];
        int r = 0;
        for (int j = 0; j < nc; j++) {
            unsigned o = cand_ord[j];
            r += (o > mo) || (o == mo && cand_idx[j] < mi);
        }
        if (r < kneed) { sel_ord[above + r] = mo; sel_idx[above + r] = mi; }
    }
    __syncthreads();
    if (tid < DOUT) {
        unsigned mo = sel_ord[tid];
        int mi = sel_idx[tid];
        int r = 0;
#pragma unroll 4
        for (int i = 0; i < DOUT; i++) {
            unsigned o = sel_ord[i];
            r += (o > mo) || (o == mo && sel_idx[i] < mi);
        }
        sh_idx[r] = mi;
        sh_tanh[r] = tanhf(scores[mi]);
    }
    __syncthreads();
    float* xt = g_xt + t * MAT;
    for (int e = tid; e < MAT; e += 1024) {
        int j = e >> 8;
        int d = e & 255;
        xt[d * DOUT + j] = embs[((size_t)t * NN + sh_idx[j]) * DIN + d] * sh_tanh[j];
    }
}

__global__ void mid2s_kernel(const float* __restrict__ embs) {
    if (blockIdx.x < TT) do_select(blockIdx.x, embs);
    else                 do_scan(blockIdx.x - TT);
}

// ===== small GEMM: 8x128 tile, K=256, up to 3 A-mats sharing B (256 thr) ======
#define KT 32
template <int NMAT>
__device__ __forceinline__ void gemmR8(const float* __restrict__ AT0,
                                       const float* __restrict__ AT1,
                                       const float* __restrict__ AT2,
                                       const float* __restrict__ Bmat,
                                       int i0, ull a0[2], ull a1[2], ull a2[2],
                                       char* sm) {
    float (*Bs)[128] = (float(*)[128])sm;                // 16 KB
    float (*As)[8]   = (float(*)[8])(sm + KT * 128 * 4); // NMAT*32*8 floats
    int tid = threadIdx.x;           // 256
    int ti = tid & 7, tj = tid >> 3;
    int brow = tid >> 5, bcol = (tid & 31) * 4;
    int akk = tid >> 3, aii = tid & 7;

    float4 pb[4];
    float pa0, pa1, pa2;
#pragma unroll
    for (int l = 0; l < 4; l++)
        pb[l] = *(const float4*)&Bmat[(brow + 8 * l) * 128 + bcol];
    pa0 = AT0[akk * DIN + i0 + aii];
    if (NMAT > 1) pa1 = AT1[akk * DIN + i0 + aii];
    if (NMAT > 2) pa2 = AT2[akk * DIN + i0 + aii];

    for (int k0 = 0; k0 < DIN; k0 += KT) {
#pragma unroll
        for (int l = 0; l < 4; l++)
            *(float4*)&Bs[brow + 8 * l][bcol] = pb[l];
        As[0 * KT + akk][aii] = pa0;
        if (NMAT > 1) As[1 * KT + akk][aii] = pa1;
        if (NMAT > 2) As[2 * KT + akk][aii] = pa2;
        __syncthreads();
        int kn = k0 + KT;
        if (kn < DIN) {
#pragma unroll
            for (int l = 0; l < 4; l++)
                pb[l] = *(const float4*)&Bmat[(kn + brow + 8 * l) * 128 + bcol];
            pa0 = AT0[(kn + akk) * DIN + i0 + aii];
            if (NMAT > 1) pa1 = AT1[(kn + akk) * DIN + i0 + aii];
            if (NMAT > 2) pa2 = AT2[(kn + akk) * DIN + i0 + aii];
        }
#pragma unroll
        for (int kk = 0; kk < KT; kk++) {
            ull b0 = *(const ull*)&Bs[kk][tj * 4 + 0];
            ull b1 = *(const ull*)&Bs[kk][tj * 4 + 2];
            {
                ull av = dup2(As[0 * KT + kk][ti]);
                asm("fma.rn.f32x2 %0, %1, %2, %0;" : "+l"(a0[0]) : "l"(av), "l"(b0));
                asm("fma.rn.f32x2 %0, %1, %2, %0;" : "+l"(a0[1]) : "l"(av), "l"(b1));
            }
            if (NMAT > 1) {
                ull av = dup2(As[1 * KT + kk][ti]);
                asm("fma.rn.f32x2 %0, %1, %2, %0;" : "+l"(a1[0]) : "l"(av), "l"(b0));
                asm("fma.rn.f32x2 %0, %1, %2, %0;" : "+l"(a1[1]) : "l"(av), "l"(b1));
            }
            if (NMAT > 2) {
                ull av = dup2(As[2 * KT + kk][ti]);
                asm("fma.rn.f32x2 %0, %1, %2, %0;" : "+l"(a2[0]) : "l"(av), "l"(b0));
                asm("fma.rn.f32x2 %0, %1, %2, %0;" : "+l"(a2[1]) : "l"(av), "l"(b1));
            }
        }
        __syncthreads();
    }
}

// ---- gruA (32 blocks): z = sig(WXz+Uz@W+bz), r = sig(WXr+Ur@W+br), rW = r*W --
__device__ __forceinline__ void dev_gruA(int t, int bx,
                                         const float* __restrict__ bz,
                                         const float* __restrict__ br,
                                         char* sm, bool wait_wx) {
    int i0 = bx * 8;
    ull a0[2] = {0, 0}, a1[2] = {0, 0};
    gemmR8<2>(g_WT + 1 * MSQ, g_WT + 3 * MSQ, (const float*)0,
              g_Wn + t * MAT, i0, a0, a1, a0, sm);
    if (wait_wx) flag_wait(&g_flagWX, 32);
    int ti = threadIdx.x & 7, tj = threadIdx.x >> 3;
    int row = i0 + ti, col = tj * 4;
    const float* WXz = g_WX + (0 * TT + t) * MAT;
    const float* WXr = g_WX + (1 * TT + t) * MAT;
    const float* Wt  = g_Wn + t * MAT;
#pragma unroll
    for (int j = 0; j < 2; j++) {
        int o = row * DOUT + col + 2 * j;
        float2 az = upk(a0[j]), ar = upk(a1[j]);
        float2 xz = *(const float2*)&WXz[o];
        float2 xr = *(const float2*)&WXr[o];
        float2 vz = *(const float2*)&bz[o];
        float2 vr = *(const float2*)&br[o];
        float2 wv = *(const float2*)&Wt[o];
        float2 z2, rw2;
        z2.x = sigmoidf_(az.x + xz.x + vz.x);
        z2.y = sigmoidf_(az.y + xz.y + vz.y);
        rw2.x = sigmoidf_(ar.x + xr.x + vr.x) * wv.x;
        rw2.y = sigmoidf_(ar.y + xr.y + vr.y) * wv.y;
        *(float2*)&g_z[o] = z2;
        *(float2*)&g_rW[o] = rw2;
    }
    flag_release(&g_flagA[t]);
}

// ---- gruB (32 blocks): h = tanh(WXh+Uh@rW+bh); Wn_{t+1} = W + z*(h-W) -------
__device__ __forceinline__ void dev_gruB(int t, int bx,
                                         const float* __restrict__ bh, char* sm) {
    flag_wait(&g_flagA[t], 32);
    int i0 = bx * 8;
    ull a0[2] = {0, 0};
    gemmR8<1>(g_WT + 5 * MSQ, (const float*)0, (const float*)0,
              g_rW, i0, a0, a0, a0, sm);
    int ti = threadIdx.x & 7, tj = threadIdx.x >> 3;
    int row = i0 + ti, col = tj * 4;
    const float* WXh = g_WX + (2 * TT + t) * MAT;
    const float* Wt  = g_Wn + t * MAT;
    float* Wnx = g_Wn + (t + 1) * MAT;
    __half* Whx = g_Wh + t * MAT;
#pragma unroll
    for (int j = 0; j < 2; j++) {
        int o = row * DOUT + col + 2 * j;
        float2 ah = upk(a0[j]);
        float2 xh = *(const float2*)&WXh[o];
        float2 vh = *(const float2*)&bh[o];
        float2 wv = *(const float2*)&Wt[o];
        float2 z2 = *(const float2*)&g_z[o];
        float hx = tanhf(ah.x + xh.x + vh.x);
        float hy = tanhf(ah.y + xh.y + vh.y);
        float2 wn;
        wn.x = wv.x + z2.x * (hx - wv.x);
        wn.y = wv.y + z2.y * (hy - wv.y);
        *(float2*)&Wnx[o] = wn;
        *(__half2*)&Whx[o] = __float22half2_rn(wn);
    }
}

// ---- CSR fill body (2500 blocks per t) ---------------------------------------
__device__ __forceinline__ void dev_fill(int t, int bx,
                                         const int* __restrict__ ei,
                                         const float* __restrict__ w) {
    int e = bx * 256 + threadIdx.x;
    const int* dst = ei + (size_t)t * 2 * EE;
    const int* src = dst + EE;
    int d = dst[e];
    int pos = atomicAdd(&g_cur[t * NN + d], 1);
    g_csr[(size_t)t * EE + pos] = make_int2(src[e], __float_as_int(w[(size_t)t * EE + e]));
}

// ================= WXG: WX GEMMs(128) | gruA0(32) | gruB0(32) | fill(0) ======
#define WXG_SMEM (KT * 128 * 4 + 3 * KT * 8 * 4)
__global__ void wxg_kernel(const int* __restrict__ ei, const float* __restrict__ w,
                           const float* __restrict__ bz, const float* __restrict__ br,
                           const float* __restrict__ bh) {
    __shared__ __align__(16) char sm[WXG_SMEM];
    int b = blockIdx.x;
    if (b < 128) {
        int t = b >> 5, i0 = (b & 31) * 8;
        ull a0[2] = {0, 0}, a1[2] = {0, 0}, a2[2] = {0, 0};
        gemmR8<3>(g_WT + 0 * MSQ, g_WT + 2 * MSQ, g_WT + 4 * MSQ,
                  g_xt + t * MAT, i0, a0, a1, a2, sm);
        int ti = threadIdx.x & 7, tj = threadIdx.x >> 3;
        int base = (i0 + ti) * DOUT + tj * 4;
#pragma unroll
        for (int j = 0; j < 2; j++) {
            *(ull*)&g_WX[(0 * TT + t) * MAT + base + 2 * j] = a0[j];
            *(ull*)&g_WX[(1 * TT + t) * MAT + base + 2 * j] = a1[j];
            *(ull*)&g_WX[(2 * TT + t) * MAT + base + 2 * j] = a2[j];
        }
        if (t == 0) flag_release(&g_flagWX);
    } else if (b < 160) {
        dev_gruA(0, b - 128, bz, br, sm, true);
    } else if (b < 192) {
        dev_gruB(0, b - 160, bh, sm);
    } else {
        dev_fill(0, b - 192, ei, w);
    }
}

// ========= tensor-core sgemm BM=32 (16-reg acc): y_t = xh_t @ Wh_t ============
#define BM 32
#define BN 128
#define SGB ((NN + BM - 1) / BM)   // 625
#define ASTRIDE 40
#define BSTRIDE 136

__device__ __forceinline__ void dev_sgemm(int t, int bx, char* sm) {
    __half* Ah = (__half*)sm;                       // [32][ASTRIDE]
    __half* Bh = (__half*)(sm + 32 * ASTRIDE * 2);  // [32][BSTRIDE]
    const __half* A = g_xh + (size_t)t * NN * DIN;
    const __half* B = g_Wh + t * MAT;
    __half* C = g_y + (size_t)t * NN * DOUT;
    int tid = threadIdx.x, lane = tid & 31, wid = tid >> 5;
    int wq = wid;                    // warp covers cols wq*16..+15, all 32 rows
    int bm = bx * BM;

    float c[2][2][4];
#pragma unroll
    for (int ma = 0; ma < 2; ma++)
#pragma unroll
        for (int na = 0; na < 2; na++)
#pragma unroll
            for (int i = 0; i < 4; i++) c[ma][na][i] = 0.0f;

    int arow = tid >> 3, acol = (tid & 7) * 4;    // 32 rows x 32 cols, uint2 each
    int agr = bm + arow;
    uint2 zero2 = make_uint2(0, 0);

    for (int k0 = 0; k0 < DIN; k0 += 32) {
        uint2 av = (agr < NN) ? *(const uint2*)&A[(size_t)agr * DIN + k0 + acol] : zero2;
        *(uint2*)&Ah[arow * ASTRIDE + acol] = av;
#pragma unroll
        for (int pp = 0; pp < 2; pp++) {
            int q = tid + pp * 256;
            int brr = q >> 4, bcc = (q & 15) * 8;
            *(uint4*)&Bh[brr * BSTRIDE + bcc] = *(const uint4*)&B[(k0 + brr) * BN + bcc];
        }
        __syncthreads();
#pragma unroll
        for (int ks = 0; ks < 32; ks += 16) {
            unsigned bf[2][2];
#pragma unroll
            for (int na = 0; na < 2; na++) {
                int r = ks + (lane & 15);
                unsigned ad = smaddr(&Bh[r * BSTRIDE + wq * 16 + na * 8]);
                asm volatile("ldmatrix.sync.aligned.m8n8.x2.trans.shared.b16 {%0,%1}, [%2];"
                             : "=r"(bf[na][0]), "=r"(bf[na][1]) : "r"(ad));
            }
#pragma unroll
            for (int ma = 0; ma < 2; ma++) {
                int mr = ma * 16 + (lane & 15);
                int kc = ks + ((lane >> 4) << 3);
                unsigned ad = smaddr(&Ah[mr * ASTRIDE + kc]);
                unsigned a0, a1, a2, a3;
                asm volatile("ldmatrix.sync.aligned.m8n8.x4.shared.b16 {%0,%1,%2,%3}, [%4];"
                             : "=r"(a0), "=r"(a1), "=r"(a2), "=r"(a3) : "r"(ad));
#pragma unroll
                for (int na = 0; na < 2; na++) {
                    asm volatile(
                        "mma.sync.aligned.m16n8k16.row.col.f32.f16.f16.f32 "
                        "{%0,%1,%2,%3}, {%4,%5,%6,%7}, {%8,%9}, {%0,%1,%2,%3};"
                        : "+f"(c[ma][na][0]), "+f"(c[ma][na][1]),
                          "+f"(c[ma][na][2]), "+f"(c[ma][na][3])
                        : "r"(a0), "r"(a1), "r"(a2), "r"(a3),
                          "r"(bf[na][0]), "r"(bf[na][1]));
                }
            }
        }
        __syncthreads();
    }
#pragma unroll
    for (int ma = 0; ma < 2; ma++) {
        int row0 = bm + ma * 16 + (lane >> 2);
#pragma unroll
        for (int na = 0; na < 2; na++) {
            int col = wq * 16 + na * 8 + (lane & 3) * 2;
            if (row0 < NN)
                *(__half2*)&C[(size_t)row0 * DOUT + col] =
                    __floats2half2_rn(c[ma][na][0], c[ma][na][1]);
            if (row0 + 8 < NN)
                *(__half2*)&C[(size_t)(row0 + 8) * DOUT + col] =
                    __floats2half2_rn(c[ma][na][2], c[ma][na][3]);
        }
    }
}

// ---- gather: 8 edge-rows in flight per warp (y(t) produced in prior launch) --
__device__ __forceinline__ void dev_gather(int t, int bx, float* __restrict__ out) {
    int node = bx * 8 + (threadIdx.x >> 5);
    int lane = threadIdx.x & 31;
    const int* off = g_off + t * (NN + 1);
    const int2* csr = g_csr + (size_t)t * EE;
    const __half* y = g_y + (size_t)t * NN * DOUT;
    int beg = off[node], end = off[node + 1];
    float4 acc = make_float4(0.f, 0.f, 0.f, 0.f);
    int e = beg;
    for (; e + 8 <= end; e += 8) {
        int2 cc[8];
        uint2 rr[8];
#pragma unroll
        for (int u = 0; u < 8; u++) cc[u] = csr[e + u];
#pragma unroll
        for (int u = 0; u < 8; u++)
            rr[u] = *(const uint2*)&y[(size_t)cc[u].x * DOUT + lane * 4];
#pragma unroll
        for (int u = 0; u < 8; u++) {
            float wv = __int_as_float(cc[u].y);
            float2 av = __half22float2(*(__half2*)&rr[u].x);
            float2 bv = __half22float2(*(__half2*)&rr[u].y);
            acc.x += wv * av.x;
            acc.y += wv * av.y;
            acc.z += wv * bv.x;
            acc.w += wv * bv.y;
        }
    }
    for (; e < end; e++) {
        int2 c0 = csr[e];
        float w0 = __int_as_float(c0.y);
        uint2 r0 = *(const uint2*)&y[(size_t)c0.x * DOUT + lane * 4];
        float2 a0 = __half22float2(*(__half2*)&r0.x), b0 = __half22float2(*(__half2*)&r0.y);
        acc.x += w0 * a0.x; acc.y += w0 * a0.y; acc.z += w0 * b0.x; acc.w += w0 * b0.y;
    }
    acc.x = (acc.x >= 0.f) ? acc.x : SLOPE * acc.x;
    acc.y = (acc.y >= 0.f) ? acc.y : SLOPE * acc.y;
    acc.z = (acc.z >= 0.f) ? acc.z : SLOPE * acc.z;
    acc.w = (acc.w >= 0.f) ? acc.w : SLOPE * acc.w;
    *(float4*)&out[((size_t)t * NN + node) * DOUT + lane * 4] = acc;
}

// ==== pipe P(t): gruA(t+1)|gruB(t+1)(spin)|sgemm(t)|fill(t+1)|gather(t-1) =====
#define PIPE_SMEM (KT * 128 * 4 + 2 * KT * 8 * 4)   // 18432 >= sgemm smem 11264
__global__ __launch_bounds__(256, 4)
void pipe_kernel(int t_sg, int t_ga, int t_fill, int has_gru,
                 const int* __restrict__ ei, const float* __restrict__ w,
                 const float* __restrict__ bz, const float* __restrict__ br,
                 const float* __restrict__ bh,
                 float* __restrict__ out) {
    __shared__ __align__(16) char sm[PIPE_SMEM];
    int b = blockIdx.x;
    if (has_gru) {
        if (b < 32) { dev_gruA(t_sg + 1, b, bz, br, sm, false); return; }
        if (b < 64) { dev_gruB(t_sg + 1, b - 32, bh, sm); return; }
        b -= 64;
    }
    if (b < SGB) { dev_sgemm(t_sg, b, sm); return; }
    b -= SGB;
    if (t_fill >= 0) {
        if (b < 2500) { dev_fill(t_fill, b, ei, w); return; }
        b -= 2500;
    }
    dev_gather(t_ga, b, out);
}

__global__ __launch_bounds__(256, 4) void gather_only_kernel(int t, float* __restrict__ out) {
    dev_gather(t, blockIdx.x, out);
}

// ---------------- launcher ----------------
extern "C" void kernel_launch(void* const* d_in, const int* in_sizes, int n_in,
                              void* d_out, int out_size) {
    const float* node_embs  = (const float*)d_in[0];
    const int*   edge_index = (const int*)d_in[1];
    const float* edge_w     = (const float*)d_in[2];
    const float* mask       = (const float*)d_in[3];
    const float* p          = (const float*)d_in[4];
    const float* Wz         = (const float*)d_in[5];
    const float* Uz         = (const float*)d_in[6];
    const float* bz         = (const float*)d_in[7];
    const float* Wr         = (const float*)d_in[8];
    const float* Ur         = (const float*)d_in[9];
    const float* br         = (const float*)d_in[10];
    const float* Wh         = (const float*)d_in[11];
    const float* Uh         = (const float*)d_in[12];
    const float* bh         = (const float*)d_in[13];
    const float* W0         = (const float*)d_in[14];
    float* out = (float*)d_out;

    front_kernel<<<FB_TOTAL, 256>>>(node_embs, p, mask, edge_index,
                                    Wz, Uz, Wr, Ur, Wh, Uh, W0);
    mid2s_kernel<<<2 * TT, 1024>>>(node_embs);
    wxg_kernel<<<192 + 2500, 256>>>(edge_index, edge_w, bz, br, bh);

    // P0: gruA(1)+gruB(1) | sgemm(0) | fill(1)
    pipe_kernel<<<64 + SGB + 2500, 256>>>(0, -1, 1, 1, edge_index, edge_w,
                                          bz, br, bh, out);
    // P1: gruA(2)+gruB(2) | sgemm(1) | fill(2) | gather(0)
    pipe_kernel<<<64 + SGB + 2500 + 2500, 256>>>(1, 0, 2, 1, edge_index, edge_w,
                                                 bz, br, bh, out);
    // P2: gruA(3)+gruB(3) | sgemm(2) | fill(3) | gather(1)
    pipe_kernel<<<64 + SGB + 2500 + 2500, 256>>>(2, 1, 3, 1, edge_index, edge_w,
                                                 bz, br, bh, out);
    // P3: sgemm(3) | gather(2)
    pipe_kernel<<<SGB + 2500, 256>>>(3, 2, -1, 0, edge_index, edge_w,
                                     bz, br, bh, out);
    gather_only_kernel<<<2500, 256>>>(3, out);
}